// round 15
// baseline (speedup 1.0000x reference)
#include <cuda_runtime.h>

#define NB     8
#define IN_CH  64
#define OUT_CH 64
#define GROUPS 8
#define FPG    8
#define H      256
#define WD     256
#define TY     16
#define TPB    2          // tiles per block (sequential)
#define SW     264        // smem row stride (floats); 264*4 bytes % 16 == 0

struct R6 { float v[6]; };

__device__ __forceinline__ R6 ldrow(const float* base) {
    // base points at S + r*SW + c0 ; window cols c0-1 .. c0+4 live at [3..8]
    R6 r;
    r.v[0] = base[3];
    float4 m = *(const float4*)(base + 4);
    r.v[1] = m.x; r.v[2] = m.y; r.v[3] = m.z; r.v[4] = m.w;
    r.v[5] = base[8];
    return r;
}

__device__ __forceinline__ void accum(float4& a, const R6& r,
                                      float w0, float w1, float w2) {
    a.x = fmaf(w0, r.v[0], a.x); a.x = fmaf(w1, r.v[1], a.x); a.x = fmaf(w2, r.v[2], a.x);
    a.y = fmaf(w0, r.v[1], a.y); a.y = fmaf(w1, r.v[2], a.y); a.y = fmaf(w2, r.v[3], a.y);
    a.z = fmaf(w0, r.v[2], a.z); a.z = fmaf(w1, r.v[3], a.z); a.z = fmaf(w2, r.v[4], a.z);
    a.w = fmaf(w0, r.v[3], a.w); a.w = fmaf(w1, r.v[4], a.w); a.w = fmaf(w2, r.v[5], a.w);
}

__global__ __launch_bounds__(256)
void dynconv(const float* __restrict__ x,
             const float* __restrict__ rep,
             const float* __restrict__ Wm,
             float* __restrict__ out) {
    __shared__ __align__(16) float S[(TY + 2) * SW];
    __shared__ float wk[FPG * 9];

    const int tid = threadIdx.x;
    const int g   = blockIdx.y;
    const int bb  = blockIdx.z;

    // ---- Tap computation once per block (amortized over TPB tiles)
    if (tid < FPG * 9) {
        const float4* r4 = (const float4*)(rep + bb * 32);
        const float4* w4 = (const float4*)(Wm + (size_t)(g * 72 + tid) * 32);
        float acc = 0.f;
#pragma unroll
        for (int i = 0; i < 8; i++) {
            float4 a = r4[i], b = w4[i];
            acc = fmaf(a.x, b.x, acc); acc = fmaf(a.y, b.y, acc);
            acc = fmaf(a.z, b.z, acc); acc = fmaf(a.w, b.w, acc);
        }
        wk[tid] = acc >= 0.f ? acc : 0.1f * acc;
    }

    const float* xg = x + ((size_t)(bb * IN_CH + g * FPG)) * H * WD;

    const int qc = tid & 63;
    const int ry = tid >> 6;
    const int c0 = qc * 4;
    const int ys = ry * 4;
    const float* Srow = S + ys * SW + c0;

#pragma unroll 1
    for (int t = 0; t < TPB; t++) {
        const int y0 = (blockIdx.x * TPB + t) * TY;

        // ---- Phase 1a: interior group-sum, float4
        for (int idx = tid; idx < (TY + 2) * (WD / 4); idx += 256) {
            int r = idx >> 6, q = idx & 63;
            int gy = y0 + r - 1;
            gy = gy < 0 ? -gy : (gy >= H ? 2 * H - 2 - gy : gy);
            const float4* p = (const float4*)(xg + (size_t)gy * WD) + q;
            float4 s = p[0];
#pragma unroll
            for (int c = 1; c < FPG; c++) {
                float4 v = p[(size_t)c * (H * WD / 4)];
                s.x += v.x; s.y += v.y; s.z += v.z; s.w += v.w;
            }
            *(float4*)&S[r * SW + 4 + 4 * q] = s;
        }
        // ---- Phase 1b: reflected halo columns
        if (tid < 2 * (TY + 2)) {
            int r = tid >> 1, side = tid & 1;
            int gy = y0 + r - 1;
            gy = gy < 0 ? -gy : (gy >= H ? 2 * H - 2 - gy : gy);
            int gx = side ? (WD - 2) : 1;
            const float* p = xg + (size_t)gy * WD + gx;
            float s = 0.f;
#pragma unroll
            for (int c = 0; c < FPG; c++) s += p[(size_t)c * H * WD];
            S[r * SW + (side ? (4 + WD) : 3)] = s;
        }
        __syncthreads();

        // ---- Phase 2
        float* outb = out + (((size_t)(bb * OUT_CH + g * FPG)) * H + y0 + ys) * WD + c0;

#pragma unroll 1
        for (int j = 0; j < FPG; j++) {
            const float* w = &wk[j * 9];
            float w0 = w[0], w1 = w[1], w2 = w[2];
            float w3 = w[3], w4 = w[4], w5 = w[5];
            float w6 = w[6], w7 = w[7], w8 = w[8];

            R6 A = ldrow(Srow);
            R6 Bw = ldrow(Srow + SW);
            float* op = outb + (size_t)j * H * WD;

#pragma unroll
            for (int yy = 0; yy < 4; yy++) {
                R6 Cw = ldrow(Srow + (yy + 2) * SW);
                float4 acc = {0.f, 0.f, 0.f, 0.f};
                accum(acc, A,  w0, w1, w2);
                accum(acc, Bw, w3, w4, w5);
                accum(acc, Cw, w6, w7, w8);
                *(float4*)(op + (size_t)yy * WD) = acc;
                A = Bw; Bw = Cw;
            }
        }
        __syncthreads();   // S reused by next tile's phase 1
    }
}

extern "C" void kernel_launch(void* const* d_in, const int* in_sizes, int n_in,
                              void* d_out, int out_size) {
    const float* x   = (const float*)d_in[0];  // [8,64,256,256]
    const float* rep = (const float*)d_in[1];  // [8,32]
    const float* Wm  = (const float*)d_in[2];  // [576,32]
    float* out = (float*)d_out;                // [8,64,256,256]

    dynconv<<<dim3(H / (TY * TPB), GROUPS, NB), 256>>>(x, rep, Wm, out);
}

// round 16
// speedup vs baseline: 1.0225x; 1.0225x over previous
#include <cuda_runtime.h>

#define NB     8
#define IN_CH  64
#define OUT_CH 64
#define GROUPS 8
#define FPG    8
#define H      256
#define WD     256
#define TY     16
#define SW     264        // smem row stride (floats); 264*4 bytes % 16 == 0

struct R6 { float v[6]; };

__device__ __forceinline__ R6 ldrow(const float* base) {
    // base points at S + r*SW + c0 ; window cols c0-1 .. c0+4 live at [3..8]
    R6 r;
    r.v[0] = base[3];
    float4 m = *(const float4*)(base + 4);
    r.v[1] = m.x; r.v[2] = m.y; r.v[3] = m.z; r.v[4] = m.w;
    r.v[5] = base[8];
    return r;
}

__device__ __forceinline__ void accum(float4& a, const R6& r,
                                      float w0, float w1, float w2) {
    a.x = fmaf(w0, r.v[0], a.x); a.x = fmaf(w1, r.v[1], a.x); a.x = fmaf(w2, r.v[2], a.x);
    a.y = fmaf(w0, r.v[1], a.y); a.y = fmaf(w1, r.v[2], a.y); a.y = fmaf(w2, r.v[3], a.y);
    a.z = fmaf(w0, r.v[2], a.z); a.z = fmaf(w1, r.v[3], a.z); a.z = fmaf(w2, r.v[4], a.z);
    a.w = fmaf(w0, r.v[3], a.w); a.w = fmaf(w1, r.v[4], a.w); a.w = fmaf(w2, r.v[5], a.w);
}

__global__ __launch_bounds__(256)
void dynconv(const float* __restrict__ x,
             const float* __restrict__ rep,
             const float* __restrict__ Wm,
             float* __restrict__ out) {
    __shared__ __align__(16) float S[(TY + 2) * SW];
    __shared__ float wk[FPG * 9];

    const int tid = threadIdx.x;
    const int y0  = blockIdx.x * TY;
    const int g   = blockIdx.y;
    const int bb  = blockIdx.z;

    // ---- Fused tap computation: leaky_relu(rep[bb] . W[g*72 + tid])
    if (tid < FPG * 9) {
        const float4* r4 = (const float4*)(rep + bb * 32);
        const float4* w4 = (const float4*)(Wm + (size_t)(g * 72 + tid) * 32);
        float acc = 0.f;
#pragma unroll
        for (int i = 0; i < 8; i++) {
            float4 a = r4[i], b = w4[i];
            acc = fmaf(a.x, b.x, acc); acc = fmaf(a.y, b.y, acc);
            acc = fmaf(a.z, b.z, acc); acc = fmaf(a.w, b.w, acc);
        }
        wk[tid] = acc >= 0.f ? acc : 0.1f * acc;
    }

    const float* xg = x + ((size_t)(bb * IN_CH + g * FPG)) * H * WD;

    // ---- Phase 1a: interior group-sum, float4
    for (int idx = tid; idx < (TY + 2) * (WD / 4); idx += 256) {
        int r = idx >> 6, q = idx & 63;
        int gy = y0 + r - 1;
        gy = gy < 0 ? -gy : (gy >= H ? 2 * H - 2 - gy : gy);
        const float4* p = (const float4*)(xg + (size_t)gy * WD) + q;
        float4 s = p[0];
#pragma unroll
        for (int c = 1; c < FPG; c++) {
            float4 v = p[(size_t)c * (H * WD / 4)];
            s.x += v.x; s.y += v.y; s.z += v.z; s.w += v.w;
        }
        *(float4*)&S[r * SW + 4 + 4 * q] = s;
    }
    // ---- Phase 1b: reflected halo columns (gx=-1 -> 1, gx=256 -> 254)
    if (tid < 2 * (TY + 2)) {
        int r = tid >> 1, side = tid & 1;
        int gy = y0 + r - 1;
        gy = gy < 0 ? -gy : (gy >= H ? 2 * H - 2 - gy : gy);
        int gx = side ? (WD - 2) : 1;
        const float* p = xg + (size_t)gy * WD + gx;
        float s = 0.f;
#pragma unroll
        for (int c = 0; c < FPG; c++) s += p[(size_t)c * H * WD];
        S[r * SW + (side ? (4 + WD) : 3)] = s;
    }
    __syncthreads();

    // ---- Phase 2: thread = (ry, qc) owns 4 cols x 4 rows per output channel j
    const int qc = tid & 63;       // column quad 0..63
    const int ry = tid >> 6;       // row slice 0..3
    const int c0 = qc * 4;
    const int ys = ry * 4;         // first output row (within tile)

    const float* Srow = S + ys * SW + c0;
    float* outb = out + (((size_t)(bb * OUT_CH + g * FPG)) * H + y0 + ys) * WD + c0;

#pragma unroll 1
    for (int j = 0; j < FPG; j++) {
        const float* w = &wk[j * 9];
        float w0 = w[0], w1 = w[1], w2 = w[2];
        float w3 = w[3], w4 = w[4], w5 = w[5];
        float w6 = w[6], w7 = w[7], w8 = w[8];

        R6 A = ldrow(Srow);
        R6 Bw = ldrow(Srow + SW);
        float* op = outb + (size_t)j * H * WD;

#pragma unroll
        for (int yy = 0; yy < 4; yy++) {
            R6 Cw = ldrow(Srow + (yy + 2) * SW);
            float4 acc = {0.f, 0.f, 0.f, 0.f};
            accum(acc, A,  w0, w1, w2);
            accum(acc, Bw, w3, w4, w5);
            accum(acc, Cw, w6, w7, w8);
            *(float4*)(op + (size_t)yy * WD) = acc;
            A = Bw; Bw = Cw;
        }
    }
}

extern "C" void kernel_launch(void* const* d_in, const int* in_sizes, int n_in,
                              void* d_out, int out_size) {
    const float* x   = (const float*)d_in[0];  // [8,64,256,256]
    const float* rep = (const float*)d_in[1];  // [8,32]
    const float* Wm  = (const float*)d_in[2];  // [576,32]
    float* out = (float*)d_out;                // [8,64,256,256]

    dynconv<<<dim3(H / TY, GROUPS, NB), 256>>>(x, rep, Wm, out);
}

// round 17
// speedup vs baseline: 1.0390x; 1.0161x over previous
#include <cuda_runtime.h>

#define NB     8
#define IN_CH  64
#define OUT_CH 64
#define GROUPS 8
#define FPG    8
#define H      256
#define WD     256
#define TY     16
#define SW     264        // smem row stride (floats); 264*4 bytes % 16 == 0

struct R6 { float v[6]; };

__device__ __forceinline__ R6 ldrow(const float* base) {
    // base points at S + r*SW + c0 ; window cols c0-1 .. c0+4 live at [3..8]
    R6 r;
    r.v[0] = base[3];
    float4 m = *(const float4*)(base + 4);
    r.v[1] = m.x; r.v[2] = m.y; r.v[3] = m.z; r.v[4] = m.w;
    r.v[5] = base[8];
    return r;
}

__device__ __forceinline__ void accum(float4& a, const R6& r,
                                      float w0, float w1, float w2) {
    a.x = fmaf(w0, r.v[0], a.x); a.x = fmaf(w1, r.v[1], a.x); a.x = fmaf(w2, r.v[2], a.x);
    a.y = fmaf(w0, r.v[1], a.y); a.y = fmaf(w1, r.v[2], a.y); a.y = fmaf(w2, r.v[3], a.y);
    a.z = fmaf(w0, r.v[2], a.z); a.z = fmaf(w1, r.v[3], a.z); a.z = fmaf(w2, r.v[4], a.z);
    a.w = fmaf(w0, r.v[3], a.w); a.w = fmaf(w1, r.v[4], a.w); a.w = fmaf(w2, r.v[5], a.w);
}

__global__ __launch_bounds__(256)
void dynconv(const float* __restrict__ x,
             const float* __restrict__ rep,
             const float* __restrict__ Wm,
             float* __restrict__ out) {
    __shared__ __align__(16) float S[(TY + 2) * SW];
    __shared__ float wk[FPG * 9];

    const int tid = threadIdx.x;
    const int y0  = blockIdx.x * TY;
    const int g   = blockIdx.y;
    const int bb  = blockIdx.z;

    // ---- Fused tap computation: leaky_relu(rep[bb] . W[g*72 + tid])
    if (tid < FPG * 9) {
        const float4* r4 = (const float4*)(rep + bb * 32);
        const float4* w4 = (const float4*)(Wm + (size_t)(g * 72 + tid) * 32);
        float acc = 0.f;
#pragma unroll
        for (int i = 0; i < 8; i++) {
            float4 a = r4[i], b = w4[i];
            acc = fmaf(a.x, b.x, acc); acc = fmaf(a.y, b.y, acc);
            acc = fmaf(a.z, b.z, acc); acc = fmaf(a.w, b.w, acc);
        }
        wk[tid] = acc >= 0.f ? acc : 0.1f * acc;
    }

    const float* xg = x + ((size_t)(bb * IN_CH + g * FPG)) * H * WD;

    // ---- Phase 1a: interior group-sum, float4
    for (int idx = tid; idx < (TY + 2) * (WD / 4); idx += 256) {
        int r = idx >> 6, q = idx & 63;
        int gy = y0 + r - 1;
        gy = gy < 0 ? -gy : (gy >= H ? 2 * H - 2 - gy : gy);
        const float4* p = (const float4*)(xg + (size_t)gy * WD) + q;
        float4 s = p[0];
#pragma unroll
        for (int c = 1; c < FPG; c++) {
            float4 v = p[(size_t)c * (H * WD / 4)];
            s.x += v.x; s.y += v.y; s.z += v.z; s.w += v.w;
        }
        *(float4*)&S[r * SW + 4 + 4 * q] = s;
    }
    // ---- Phase 1b: reflected halo columns (gx=-1 -> 1, gx=256 -> 254)
    if (tid < 2 * (TY + 2)) {
        int r = tid >> 1, side = tid & 1;
        int gy = y0 + r - 1;
        gy = gy < 0 ? -gy : (gy >= H ? 2 * H - 2 - gy : gy);
        int gx = side ? (WD - 2) : 1;
        const float* p = xg + (size_t)gy * WD + gx;
        float s = 0.f;
#pragma unroll
        for (int c = 0; c < FPG; c++) s += p[(size_t)c * H * WD];
        S[r * SW + (side ? (4 + WD) : 3)] = s;
    }
    __syncthreads();

    // ---- Phase 2: thread = (ry, qc) owns 4 cols x 4 rows per output channel j
    const int qc = tid & 63;       // column quad 0..63
    const int ry = tid >> 6;       // row slice 0..3
    const int c0 = qc * 4;
    const int ys = ry * 4;         // first output row (within tile)

    const float* Srow = S + ys * SW + c0;
    float* outb = out + (((size_t)(bb * OUT_CH + g * FPG)) * H + y0 + ys) * WD + c0;

#pragma unroll 1
    for (int j = 0; j < FPG; j++) {
        const float* w = &wk[j * 9];
        float w0 = w[0], w1 = w[1], w2 = w[2];
        float w3 = w[3], w4 = w[4], w5 = w[5];
        float w6 = w[6], w7 = w[7], w8 = w[8];

        R6 A = ldrow(Srow);
        R6 Bw = ldrow(Srow + SW);
        float* op = outb + (size_t)j * H * WD;

#pragma unroll
        for (int yy = 0; yy < 4; yy++) {
            R6 Cw = ldrow(Srow + (yy + 2) * SW);
            float4 acc = {0.f, 0.f, 0.f, 0.f};
            accum(acc, A,  w0, w1, w2);
            accum(acc, Bw, w3, w4, w5);
            accum(acc, Cw, w6, w7, w8);
            *(float4*)(op + (size_t)yy * WD) = acc;
            A = Bw; Bw = Cw;
        }
    }
}

extern "C" void kernel_launch(void* const* d_in, const int* in_sizes, int n_in,
                              void* d_out, int out_size) {
    const float* x   = (const float*)d_in[0];  // [8,64,256,256]
    const float* rep = (const float*)d_in[1];  // [8,32]
    const float* Wm  = (const float*)d_in[2];  // [576,32]
    float* out = (float*)d_out;                // [8,64,256,256]

    dynconv<<<dim3(H / TY, GROUPS, NB), 256>>>(x, rep, Wm, out);
}